// round 4
// baseline (speedup 1.0000x reference)
#include <cuda_runtime.h>
#include <cuda_bf16.h>
#include <math.h>

// Problem constants (shapes fixed by the reference)
#define MAX_N 50000
#define MAX_E 800000
#define MAX_G 16
#define NODE_DIM 128
#define HID 64
#define HEADS 3
#define FDIM 192            // HEADS*HID
#define NEG_SLOPE 0.2f

// ---------------- device scratch (static, no runtime alloc) ----------------
__device__ float g_feat[(size_t)MAX_N * FDIM];   // 38.4 MB
__device__ float g_el[MAX_N * 3];
__device__ float g_er[MAX_N * 3];
__device__ int   g_deg[MAX_N];
__device__ int   g_rowoff[MAX_N + 1];
__device__ int   g_cursor[MAX_N];
__device__ int   g_csrsrc[MAX_E];
__device__ float g_pool[MAX_G * HID];
__device__ float g_gcount[MAX_G];

// ---------------- init ----------------
__global__ void k_init(int N, int G) {
    int i = blockIdx.x * blockDim.x + threadIdx.x;
    int stride = gridDim.x * blockDim.x;
    for (int j = i; j < N; j += stride) g_deg[j] = 0;
    if (i < G * HID) g_pool[i] = 0.f;
    if (i < G) g_gcount[i] = 0.f;
}

// ---------------- K1: feat = h @ fc_w^T, fused el/er ----------------
// block: 128 threads, 128 nodes (1 node/thread).
// smem: h tile node-major [128][132] (pad 4 for conflict-free LDS.128),
//       weight quarter [48 rows][32 float4], attn_l/attn_r flat [192] each.
#define K1_HS_FLOATS (128 * 132)
#define K1_WS_FLOATS (48 * 32 * 4)
#define K1_SMEM_BYTES ((K1_HS_FLOATS + K1_WS_FLOATS + 2 * FDIM) * 4)

__global__ void __launch_bounds__(128) k_gemm(
    const float* __restrict__ h, const float* __restrict__ fc_w,
    const float* __restrict__ attn_l, const float* __restrict__ attn_r, int N)
{
    extern __shared__ float sm[];
    float*  h_s = sm;                               // [128][132]
    float4* w_s = (float4*)(sm + K1_HS_FLOATS);     // [48][32]
    float*  al  = sm + K1_HS_FLOATS + K1_WS_FLOATS; // [192]
    float*  ar  = al + FDIM;                        // [192]

    const int t = threadIdx.x;
    const int node = blockIdx.x * 128 + t;
    const bool valid = node < N;

    // cooperative h-tile load: row-by-row, coalesced, stored node-major
    const int base = blockIdx.x * 128;
    #pragma unroll 4
    for (int r = 0; r < 128; r++) {
        int n0 = base + r;
        float v = (n0 < N) ? h[(size_t)n0 * NODE_DIM + t] : 0.f;
        h_s[r * 132 + t] = v;
    }
    for (int i = t; i < FDIM; i += 128) { al[i] = attn_l[i]; ar[i] = attn_r[i]; }

    float el_acc[HEADS] = {0.f, 0.f, 0.f};
    float er_acc[HEADS] = {0.f, 0.f, 0.f};

    const float4* fw4 = (const float4*)fc_w;

    #pragma unroll
    for (int q = 0; q < 4; q++) {
        __syncthreads();   // h_s ready (q=0) / previous quarter done (q>0)
        // load weight quarter: rows q*48 .. q*48+47, as float4
        for (int i = t; i < 48 * 32; i += 128)
            w_s[i] = fw4[q * 48 * 32 + i];
        __syncthreads();

        float acc[48];
        #pragma unroll
        for (int i = 0; i < 48; i++) acc[i] = 0.f;

        for (int k = 0; k < 128; k += 4) {
            float4 hv = *(const float4*)&h_s[t * 132 + k];
            int k4 = k >> 2;
            #pragma unroll
            for (int c = 0; c < 48; c++) {
                float4 w4 = w_s[c * 32 + k4];
                acc[c] += hv.x * w4.x + hv.y * w4.y + hv.z * w4.z + hv.w * w4.w;
            }
        }

        const int c0 = q * 48;
        #pragma unroll
        for (int i = 0; i < 48; i++) {
            const int c = c0 + i;
            const int hd = c >> 6;   // compile-time (q, i unrolled)
            el_acc[hd] += acc[i] * al[c];
            er_acc[hd] += acc[i] * ar[c];
        }
        if (valid) {
            float* fout = &g_feat[(size_t)node * FDIM + c0];
            #pragma unroll
            for (int i = 0; i < 48; i += 4) {
                float4 v = make_float4(acc[i], acc[i+1], acc[i+2], acc[i+3]);
                *(float4*)(fout + i) = v;
            }
        }
    }

    if (valid) {
        #pragma unroll
        for (int hd = 0; hd < HEADS; hd++) {
            g_el[node * 3 + hd] = el_acc[hd];
            g_er[node * 3 + hd] = er_acc[hd];
        }
    }
}

// ---------------- K2: CSR build ----------------
__global__ void k_degree(const int* __restrict__ dst, int E) {
    int i = blockIdx.x * blockDim.x + threadIdx.x;
    if (i < E) atomicAdd(&g_deg[dst[i]], 1);
}

__global__ void k_scan(int N) {
    __shared__ int wsum[32];
    __shared__ int s_carry, s_total;
    const int t = threadIdx.x, lane = t & 31, w = t >> 5;
    if (t == 0) s_carry = 0;
    __syncthreads();
    for (int base = 0; base < N; base += 1024) {
        int idx = base + t;
        int v = (idx < N) ? g_deg[idx] : 0;
        int x = v;
        #pragma unroll
        for (int o = 1; o < 32; o <<= 1) {
            int y = __shfl_up_sync(0xffffffffu, x, o);
            if (lane >= o) x += y;
        }
        if (lane == 31) wsum[w] = x;
        __syncthreads();
        if (w == 0) {
            int s = wsum[lane], sc = s;
            #pragma unroll
            for (int o = 1; o < 32; o <<= 1) {
                int y = __shfl_up_sync(0xffffffffu, sc, o);
                if (lane >= o) sc += y;
            }
            if (lane == 31) s_total = sc;
            wsum[lane] = sc - s;      // exclusive warp offsets
        }
        __syncthreads();
        int excl = x - v + wsum[w] + s_carry;
        if (idx < N) { g_rowoff[idx] = excl; g_cursor[idx] = excl; }
        __syncthreads();
        if (t == 0) s_carry += s_total;
        __syncthreads();
    }
    if (t == 0) g_rowoff[N] = s_carry;
}

__global__ void k_scatter(const int* __restrict__ src, const int* __restrict__ dst, int E) {
    int i = blockIdx.x * blockDim.x + threadIdx.x;
    if (i < E) {
        int d = dst[i];
        int pos = atomicAdd(&g_cursor[d], 1);
        g_csrsrc[pos] = src[i];
    }
}

// ---------------- K3: fused GAT edge-softmax + aggregation + pool ----------------
__device__ __forceinline__ float leaky(float x) {
    return x > 0.f ? x : NEG_SLOPE * x;
}

__global__ void __launch_bounds__(256) k_gat(
    const int* __restrict__ graph_id, const float* __restrict__ bias, int N)
{
    const int gw = (blockIdx.x * blockDim.x + threadIdx.x) >> 5;
    const int lane = threadIdx.x & 31;
    if (gw >= N) return;
    const int node = gw;
    const int begin = g_rowoff[node];
    const int end   = g_rowoff[node + 1];

    const float er0 = g_er[node * 3 + 0];
    const float er1 = g_er[node * 3 + 1];
    const float er2 = g_er[node * 3 + 2];

    // pass 1: per-head max of leaky(el[src]+er[node])
    float m0 = -1e30f, m1 = -1e30f, m2 = -1e30f;
    #pragma unroll 4
    for (int i = begin; i < end; i++) {
        int s = g_csrsrc[i];
        m0 = fmaxf(m0, leaky(g_el[s * 3 + 0] + er0));
        m1 = fmaxf(m1, leaky(g_el[s * 3 + 1] + er1));
        m2 = fmaxf(m2, leaky(g_el[s * 3 + 2] + er2));
    }

    // pass 2: exp-sum + unnormalized weighted feature accumulation
    float s0 = 0.f, s1 = 0.f, s2 = 0.f;
    float a0 = 0.f, a1 = 0.f, a2 = 0.f, a3 = 0.f, a4 = 0.f, a5 = 0.f;
    #pragma unroll 2
    for (int i = begin; i < end; i++) {
        int s = g_csrsrc[i];
        float e0 = __expf(leaky(g_el[s * 3 + 0] + er0) - m0);
        float e1 = __expf(leaky(g_el[s * 3 + 1] + er1) - m1);
        float e2 = __expf(leaky(g_el[s * 3 + 2] + er2) - m2);
        s0 += e0; s1 += e1; s2 += e2;
        const float* fr = &g_feat[(size_t)s * FDIM];
        a0 += e0 * fr[lane];
        a1 += e0 * fr[lane + 32];
        a2 += e1 * fr[lane + 64];
        a3 += e1 * fr[lane + 96];
        a4 += e2 * fr[lane + 128];
        a5 += e2 * fr[lane + 160];
    }

    const bool has = end > begin;
    const float i0 = has ? 1.f / s0 : 0.f;
    const float i1 = has ? 1.f / s1 : 0.f;
    const float i2 = has ? 1.f / s2 : 0.f;

    // head-mean (+ bias, reshape(3,64)) -> h_d dims (lane) and (lane+32)
    const float third = 1.f / 3.f;
    float hd0 = (a0 * i0 + a2 * i1 + a4 * i2
                 + bias[lane] + bias[64 + lane] + bias[128 + lane]) * third;
    float hd1 = (a1 * i0 + a3 * i1 + a5 * i2
                 + bias[32 + lane] + bias[96 + lane] + bias[160 + lane]) * third;

    const int g = graph_id[node];
    atomicAdd(&g_pool[g * HID + lane], hd0);
    atomicAdd(&g_pool[g * HID + 32 + lane], hd1);
    if (lane == 0) atomicAdd(&g_gcount[g], 1.f);
}

// ---------------- K4: final MLP + sigmoid ----------------
__global__ void k_final(
    const float* __restrict__ z, const float* __restrict__ lin1_w,
    const float* __restrict__ lin1_b, const float* __restrict__ lin2_w,
    const float* __restrict__ lin2_b, float* __restrict__ out, int G)
{
    const int w = threadIdx.x >> 5;
    const int lane = threadIdx.x & 31;
    if (w >= G) return;

    // z1[j] = z[w] . lin1_w[j] + lin1_b[j], for j = lane, lane+32
    float z1a = lin1_b[lane], z1b = lin1_b[lane + 32];
    const float* zr = &z[w * 128];
    const float* w1a = &lin1_w[lane * 128];
    const float* w1b = &lin1_w[(lane + 32) * 128];
    #pragma unroll 4
    for (int k = 0; k < 128; k++) {
        float zv = zr[k];
        z1a += zv * w1a[k];
        z1b += zv * w1b[k];
    }

    float cnt = g_gcount[w];
    float invc = 1.f / fmaxf(cnt, 1.f);
    float pa = g_pool[w * HID + lane] * invc;
    float pb = g_pool[w * HID + 32 + lane] * invc;

    float part = lin2_w[lane] * pa + lin2_w[32 + lane] * pb
               + lin2_w[64 + lane] * z1a + lin2_w[96 + lane] * z1b;
    #pragma unroll
    for (int o = 16; o > 0; o >>= 1)
        part += __shfl_down_sync(0xffffffffu, part, o);

    if (lane == 0) {
        float v = part + lin2_b[0];
        out[w] = 1.f / (1.f + expf(-v));
    }
}

// ---------------- launch ----------------
extern "C" void kernel_launch(void* const* d_in, const int* in_sizes, int n_in,
                              void* d_out, int out_size)
{
    const float* h        = (const float*)d_in[0];
    const float* z        = (const float*)d_in[1];
    const int*   src      = (const int*)  d_in[2];
    const int*   dst      = (const int*)  d_in[3];
    const int*   graph_id = (const int*)  d_in[4];
    const float* fc_w     = (const float*)d_in[5];
    const float* attn_l   = (const float*)d_in[6];
    const float* attn_r   = (const float*)d_in[7];
    const float* bias     = (const float*)d_in[8];
    const float* lin1_w   = (const float*)d_in[9];
    const float* lin1_b   = (const float*)d_in[10];
    const float* lin2_w   = (const float*)d_in[11];
    const float* lin2_b   = (const float*)d_in[12];

    const int N = in_sizes[0] / NODE_DIM;   // 50000
    const int E = in_sizes[2];              // 800000
    const int G = in_sizes[1] / 128;        // 16

    cudaFuncSetAttribute(k_gemm, cudaFuncAttributeMaxDynamicSharedMemorySize,
                         K1_SMEM_BYTES);

    k_init<<<64, 256>>>(N, G);
    k_gemm<<<(N + 127) / 128, 128, K1_SMEM_BYTES>>>(h, fc_w, attn_l, attn_r, N);
    k_degree<<<(E + 255) / 256, 256>>>(dst, E);
    k_scan<<<1, 1024>>>(N);
    k_scatter<<<(E + 255) / 256, 256>>>(src, dst, E);
    {
        int nwarps = N;
        int blocks = (nwarps * 32 + 255) / 256;
        k_gat<<<blocks, 256>>>(graph_id, bias, N);
    }
    k_final<<<1, 32 * G>>>(z, lin1_w, lin1_b, lin2_w, lin2_b, (float*)d_out, G);
}